// round 11
// baseline (speedup 1.0000x reference)
#include <cuda_runtime.h>
#include <cuda_bf16.h>
#include <cstdint>

// CombPool2d: out = (w_avg^2)*avg_pool2x2(x) + (w_max^2)*max_pool2x2(x)
// x: (16, 192, 224, 224) fp32 ; w_avg, w_max: (1,192,1,1) ; out: (16,192,112,112)
//
// HBM-streaming kernel, 8 output pixels per thread:
//   reads 4x float4 from input row 2h' and 4x float4 from row 2h'+1 (MLP=8),
//   writes two float4. Fully coalesced, 16B-aligned, streaming cache hints.
//   Grid is EXACT: 3072 planes * 1568 octs = 4,816,896 threads = 18,816 x 256
//   -> no tail guard, no predicated-off threads.

#define C_DIM       192
#define H_IN        224
#define W_IN        224
#define H_OUT       112
#define W_OUT       112
#define OCTS_W      (W_OUT / 8)            // 14 octs (8-pixel groups) per row
#define OCTS_PLANE  (H_OUT * OCTS_W)       // 1568 octs per (b,c) plane
#define THREADS     256

__global__ __launch_bounds__(THREADS)
void combpool2d_kernel(const float* __restrict__ x,
                       const float* __restrict__ w_avg,
                       const float* __restrict__ w_max,
                       float* __restrict__ out)
{
    const unsigned idx = blockIdx.x * THREADS + threadIdx.x;  // global oct index

    const unsigned bc  = idx / OCTS_PLANE;                    // plane 0..3071
    const unsigned rem = idx % OCTS_PLANE;
    const unsigned hp  = rem / OCTS_W;                        // output row 0..111
    const unsigned wo  = rem % OCTS_W;                        // oct column 0..13
    const unsigned c   = bc % C_DIM;

    // Input rows 2hp and 2hp+1; row stride 224 floats = 896 B (16B-aligned).
    const size_t in_plane = (size_t)bc * (H_IN * W_IN);
    const float4* r0 = reinterpret_cast<const float4*>(x + in_plane + (size_t)(2 * hp)     * W_IN) + 4 * wo;
    const float4* r1 = reinterpret_cast<const float4*>(x + in_plane + (size_t)(2 * hp + 1) * W_IN) + 4 * wo;

    // Eight independent 128-bit streaming loads (front-batched, MLP=8).
    const float4 a0 = __ldcs(r0);
    const float4 a1 = __ldcs(r0 + 1);
    const float4 a2 = __ldcs(r0 + 2);
    const float4 a3 = __ldcs(r0 + 3);
    const float4 b0 = __ldcs(r1);
    const float4 b1 = __ldcs(r1 + 1);
    const float4 b2 = __ldcs(r1 + 2);
    const float4 b3 = __ldcs(r1 + 3);

    float ca = __ldg(w_avg + c); ca *= ca;
    float cm = __ldg(w_max + c); cm *= cm;

    // Pixels 0..3 from (a0,b0),(a1,b1); pixels 4..7 from (a2,b2),(a3,b3).
    float4 o0, o1;
    {
        const float avg0 = (a0.x + a0.y + b0.x + b0.y) * 0.25f;
        const float mx0  = fmaxf(fmaxf(a0.x, a0.y), fmaxf(b0.x, b0.y));
        const float avg1 = (a0.z + a0.w + b0.z + b0.w) * 0.25f;
        const float mx1  = fmaxf(fmaxf(a0.z, a0.w), fmaxf(b0.z, b0.w));
        const float avg2 = (a1.x + a1.y + b1.x + b1.y) * 0.25f;
        const float mx2  = fmaxf(fmaxf(a1.x, a1.y), fmaxf(b1.x, b1.y));
        const float avg3 = (a1.z + a1.w + b1.z + b1.w) * 0.25f;
        const float mx3  = fmaxf(fmaxf(a1.z, a1.w), fmaxf(b1.z, b1.w));
        o0.x = fmaf(ca, avg0, cm * mx0);
        o0.y = fmaf(ca, avg1, cm * mx1);
        o0.z = fmaf(ca, avg2, cm * mx2);
        o0.w = fmaf(ca, avg3, cm * mx3);
    }
    {
        const float avg0 = (a2.x + a2.y + b2.x + b2.y) * 0.25f;
        const float mx0  = fmaxf(fmaxf(a2.x, a2.y), fmaxf(b2.x, b2.y));
        const float avg1 = (a2.z + a2.w + b2.z + b2.w) * 0.25f;
        const float mx1  = fmaxf(fmaxf(a2.z, a2.w), fmaxf(b2.z, b2.w));
        const float avg2 = (a3.x + a3.y + b3.x + b3.y) * 0.25f;
        const float mx2  = fmaxf(fmaxf(a3.x, a3.y), fmaxf(b3.x, b3.y));
        const float avg3 = (a3.z + a3.w + b3.z + b3.w) * 0.25f;
        const float mx3  = fmaxf(fmaxf(a3.z, a3.w), fmaxf(b3.z, b3.w));
        o1.x = fmaf(ca, avg0, cm * mx0);
        o1.y = fmaf(ca, avg1, cm * mx1);
        o1.z = fmaf(ca, avg2, cm * mx2);
        o1.w = fmaf(ca, avg3, cm * mx3);
    }

    const size_t out_plane = (size_t)bc * (H_OUT * W_OUT);
    float4* orow = reinterpret_cast<float4*>(out + out_plane + (size_t)hp * W_OUT) + 2 * wo;
    __stcs(orow,     o0);
    __stcs(orow + 1, o1);
}

extern "C" void kernel_launch(void* const* d_in, const int* in_sizes, int n_in,
                              void* d_out, int out_size)
{
    const float* x     = (const float*)d_in[0];
    const float* w_avg = (const float*)d_in[1];
    const float* w_max = (const float*)d_in[2];
    float* out = (float*)d_out;

    const int num_planes = in_sizes[0] / (H_IN * W_IN);        // 3072
    const unsigned total_octs = (unsigned)num_planes * OCTS_PLANE;
    const unsigned blocks = total_octs / THREADS;              // exact: 18816

    combpool2d_kernel<<<blocks, THREADS>>>(x, w_avg, w_max, out);
}

// round 12
// speedup vs baseline: 1.2702x; 1.2702x over previous
#include <cuda_runtime.h>
#include <cuda_bf16.h>
#include <cstdint>

// CombPool2d: out = (w_avg^2)*avg_pool2x2(x) + (w_max^2)*max_pool2x2(x)
// x: (16, 192, 224, 224) fp32 ; w_avg, w_max: (1,192,1,1) ; out: (16,192,112,112)
//
// HBM-streaming kernel. Each thread computes 8 output pixels from 4 DIFFERENT
// output rows (h, h+28, h+56, h+84) at one float4 column:
//   - 8 independent LDG.128 (MLP=8), all with 16B lane stride -> each warp-wide
//     load touches exactly 4 cache lines (perfect coalescing; fixes the R11
//     64B-stride L1tex blowup).
//   - 4 contiguous STG.64.
// Grid is exact: 3072 planes * 28 * 56 = 18,816 blocks x 256, no tail.

#define C_DIM       192
#define H_IN        224
#define W_IN        224
#define H_OUT       112
#define W_OUT       112
#define PAIRS_W     (W_OUT / 2)            // 56 float4 columns per row-pair
#define HGROUP      (H_OUT / 4)            // 28 base rows
#define WORK_PLANE  (HGROUP * PAIRS_W)     // 1568 work items per plane
#define ROW4_IN     (W_IN / 4)             // 56 float4s per input row
#define THREADS     256

__device__ __forceinline__ float2 pool2(const float4 a, const float4 b,
                                        const float ca, const float cm)
{
    // Two output pixels from windows {a.x,a.y,b.x,b.y} and {a.z,a.w,b.z,b.w}
    float2 o;
    const float avg0 = (a.x + a.y + b.x + b.y) * 0.25f;
    const float mx0  = fmaxf(fmaxf(a.x, a.y), fmaxf(b.x, b.y));
    const float avg1 = (a.z + a.w + b.z + b.w) * 0.25f;
    const float mx1  = fmaxf(fmaxf(a.z, a.w), fmaxf(b.z, b.w));
    o.x = fmaf(ca, avg0, cm * mx0);
    o.y = fmaf(ca, avg1, cm * mx1);
    return o;
}

__global__ __launch_bounds__(THREADS)
void combpool2d_kernel(const float* __restrict__ x,
                       const float* __restrict__ w_avg,
                       const float* __restrict__ w_max,
                       float* __restrict__ out)
{
    const unsigned idx = blockIdx.x * THREADS + threadIdx.x;

    const unsigned bc  = idx / WORK_PLANE;                 // plane 0..3071
    const unsigned rem = idx % WORK_PLANE;
    const unsigned h   = rem / PAIRS_W;                    // base row 0..27
    const unsigned wp  = rem % PAIRS_W;                    // float4 col 0..55
    const unsigned c   = bc % C_DIM;

    // Plane bases in float4 / float2 units.
    const float4* in4 = reinterpret_cast<const float4*>(x)
                      + (size_t)bc * (H_IN * W_IN / 4);
    // Row-pair r occupies input float4s [2r*56, 2r*56+112); row1 = row0 + 56.
    const float4* p0 = in4 + (size_t)(2 * h)      * ROW4_IN + wp;   // rows h
    const float4* p1 = in4 + (size_t)(2 * h + 56) * ROW4_IN + wp;   // rows h+28
    const float4* p2 = in4 + (size_t)(2 * h + 112) * ROW4_IN + wp;  // rows h+56
    const float4* p3 = in4 + (size_t)(2 * h + 168) * ROW4_IN + wp;  // rows h+84

    // Eight independent, perfectly-coalesced 128-bit streaming loads (MLP=8).
    const float4 a0 = __ldcs(p0);
    const float4 b0 = __ldcs(p0 + ROW4_IN);
    const float4 a1 = __ldcs(p1);
    const float4 b1 = __ldcs(p1 + ROW4_IN);
    const float4 a2 = __ldcs(p2);
    const float4 b2 = __ldcs(p2 + ROW4_IN);
    const float4 a3 = __ldcs(p3);
    const float4 b3 = __ldcs(p3 + ROW4_IN);

    float ca = __ldg(w_avg + c); ca *= ca;
    float cm = __ldg(w_max + c); cm *= cm;

    const float2 o0 = pool2(a0, b0, ca, cm);
    const float2 o1 = pool2(a1, b1, ca, cm);
    const float2 o2 = pool2(a2, b2, ca, cm);
    const float2 o3 = pool2(a3, b3, ca, cm);

    float2* out2 = reinterpret_cast<float2*>(out)
                 + (size_t)bc * (H_OUT * W_OUT / 2);
    // Output row r starts at float2 index r*56.
    __stcs(out2 + (size_t)(h)      * PAIRS_W + wp, o0);
    __stcs(out2 + (size_t)(h + 28) * PAIRS_W + wp, o1);
    __stcs(out2 + (size_t)(h + 56) * PAIRS_W + wp, o2);
    __stcs(out2 + (size_t)(h + 84) * PAIRS_W + wp, o3);
}

extern "C" void kernel_launch(void* const* d_in, const int* in_sizes, int n_in,
                              void* d_out, int out_size)
{
    const float* x     = (const float*)d_in[0];
    const float* w_avg = (const float*)d_in[1];
    const float* w_max = (const float*)d_in[2];
    float* out = (float*)d_out;

    const int num_planes = in_sizes[0] / (H_IN * W_IN);        // 3072
    const unsigned total = (unsigned)num_planes * WORK_PLANE;  // 4,816,896
    const unsigned blocks = total / THREADS;                   // exact: 18,816

    combpool2d_kernel<<<blocks, THREADS>>>(x, w_avg, w_max, out);
}

// round 14
// speedup vs baseline: 1.2967x; 1.0208x over previous
#include <cuda_runtime.h>
#include <cuda_bf16.h>
#include <cstdint>

// CombPool2d: out = (w_avg^2)*avg_pool2x2(x) + (w_max^2)*max_pool2x2(x)
// x: (16, 192, 224, 224) fp32 ; w_avg, w_max: (1,192,1,1) ; out: (16,192,112,112)
//
// HBM-streaming kernel. Each thread computes a 2x2 block of OUTPUT pixels:
//   - loads float4 from 4 CONSECUTIVE input rows (4h2..4h2+3) at one column
//     -> 4 independent LDG.128 (MLP=4), 16B lane stride: each warp-wide load
//        touches exactly 4 cache lines (perfect coalescing).
//   - stores 2 float2 to adjacent output rows (2h2, 2h2+1), 2 lines/store.
// Grid is exact: 3072 planes * 56 row-pairs * 56 cols = 37,632 blocks x 256,
// zero tail (R10 wasted 4.7% of threads on the bounds guard).

#define C_DIM       192
#define H_IN        224
#define W_IN        224
#define H_OUT       112
#define W_OUT       112
#define COLS4       (W_IN / 4)             // 56 float4s per input row
#define PAIRS_W     (W_OUT / 2)            // 56 float2s per output row
#define RP          (H_OUT / 2)            // 56 output row-pairs
#define WORK_PLANE  (RP * PAIRS_W)         // 3136 work items per plane
#define THREADS     256

__device__ __forceinline__ float2 pool2(const float4 a, const float4 b,
                                        const float ca, const float cm)
{
    float2 o;
    const float avg0 = (a.x + a.y + b.x + b.y) * 0.25f;
    const float mx0  = fmaxf(fmaxf(a.x, a.y), fmaxf(b.x, b.y));
    const float avg1 = (a.z + a.w + b.z + b.w) * 0.25f;
    const float mx1  = fmaxf(fmaxf(a.z, a.w), fmaxf(b.z, b.w));
    o.x = fmaf(ca, avg0, cm * mx0);
    o.y = fmaf(ca, avg1, cm * mx1);
    return o;
}

__global__ __launch_bounds__(THREADS)
void combpool2d_kernel(const float* __restrict__ x,
                       const float* __restrict__ w_avg,
                       const float* __restrict__ w_max,
                       float* __restrict__ out)
{
    const unsigned idx = blockIdx.x * THREADS + threadIdx.x;

    const unsigned bc  = idx / WORK_PLANE;                 // plane 0..3071
    const unsigned rem = idx % WORK_PLANE;
    const unsigned h2  = rem / PAIRS_W;                    // output row-pair 0..55
    const unsigned wp  = rem % PAIRS_W;                    // float4/float2 col 0..55
    const unsigned c   = bc % C_DIM;

    // Input: 4 consecutive rows 4h2..4h2+3 at float4 column wp.
    const float4* in4 = reinterpret_cast<const float4*>(x)
                      + (size_t)bc * (H_IN * W_IN / 4)
                      + (size_t)(4 * h2) * COLS4 + wp;

    // Four independent, perfectly-coalesced 128-bit streaming loads (MLP=4).
    const float4 a = __ldcs(in4);                 // row 4h2
    const float4 b = __ldcs(in4 + COLS4);         // row 4h2+1
    const float4 d = __ldcs(in4 + 2 * COLS4);     // row 4h2+2
    const float4 e = __ldcs(in4 + 3 * COLS4);     // row 4h2+3

    float ca = __ldg(w_avg + c); ca *= ca;
    float cm = __ldg(w_max + c); cm *= cm;

    const float2 o0 = pool2(a, b, ca, cm);        // output row 2h2
    const float2 o1 = pool2(d, e, ca, cm);        // output row 2h2+1

    float2* out2 = reinterpret_cast<float2*>(out)
                 + (size_t)bc * (H_OUT * W_OUT / 2)
                 + (size_t)(2 * h2) * PAIRS_W + wp;
    __stcs(out2,           o0);
    __stcs(out2 + PAIRS_W, o1);
}

extern "C" void kernel_launch(void* const* d_in, const int* in_sizes, int n_in,
                              void* d_out, int out_size)
{
    const float* x     = (const float*)d_in[0];
    const float* w_avg = (const float*)d_in[1];
    const float* w_max = (const float*)d_in[2];
    float* out = (float*)d_out;

    const int num_planes = in_sizes[0] / (H_IN * W_IN);        // 3072
    const unsigned total = (unsigned)num_planes * WORK_PLANE;  // 9,633,792
    const unsigned blocks = total / THREADS;                   // exact: 37,632

    combpool2d_kernel<<<blocks, THREADS>>>(x, w_avg, w_max, out);
}